// round 1
// baseline (speedup 1.0000x reference)
#include <cuda_runtime.h>
#include <math.h>

#define D     512
#define NE    8192
#define NMAX  32768
#define BM    64
#define BN    256
#define KT    64
#define EPAD  68        // stride % 32 == 4 -> conflict-free float4 phases
#define BETA  0.25f

__device__ float g_inv[NE];
__device__ float g_counts[NE];
__device__ int   g_idx[NMAX];
__device__ float g_loss;

// ---------------- zero scratch ----------------
__global__ void zero_kernel() {
    int i = blockIdx.x * blockDim.x + threadIdx.x;
    if (i < NE) g_counts[i] = 0.0f;
    if (i == 0) g_loss = 0.0f;
}

// ---------------- emb inverse norms ----------------
__global__ void embnorm_kernel(const float* __restrict__ emb) {
    int e = blockIdx.x;
    const float4* row = (const float4*)(emb + (size_t)e * D);
    float ss = 0.0f;
    for (int i = threadIdx.x; i < D / 4; i += 128) {
        float4 v = row[i];
        ss += v.x * v.x + v.y * v.y + v.z * v.z + v.w * v.w;
    }
    for (int o = 16; o; o >>= 1) ss += __shfl_down_sync(0xffffffffu, ss, o);
    __shared__ float s[4];
    if ((threadIdx.x & 31) == 0) s[threadIdx.x >> 5] = ss;
    __syncthreads();
    if (threadIdx.x == 0) {
        ss = s[0] + s[1] + s[2] + s[3];
        g_inv[e] = 1.0f / fmaxf(sqrtf(ss), 1e-12f);
    }
}

// ---------------- fused GEMM + argmax ----------------
// CTA: 64 z rows (full K in smem), streams emb in 256-col tiles, KT=64 k-chunks.
// 256 threads, 8x8 micro-tile each (thread grid 8 row-groups x 32 col-lanes).
extern __shared__ float smem_dyn[];

__global__ void __launch_bounds__(256, 1)
argmax_kernel(const float* __restrict__ z, const float* __restrict__ emb) {
    float* z_s = smem_dyn;                 // [BM][D]        = 128 KB
    float* e_s = smem_dyn + BM * D;        // [BN][EPAD]     ~ 68 KB

    const int tid  = threadIdx.x;
    const int ty   = tid >> 5;             // 0..7  (row group; rows ty*8..ty*8+7)
    const int tx   = tid & 31;             // 0..31 (col lane; cols tx + 32*c)
    const int row0 = blockIdx.x * BM;

    // load the z slab (coalesced float4)
    {
        const float4* zg  = (const float4*)(z + (size_t)row0 * D);
        float4*       zs4 = (float4*)z_s;
        for (int i = tid; i < BM * D / 4; i += 256) zs4[i] = zg[i];
    }
    __syncthreads();

    float bestv[8];
    int   besti[8];
#pragma unroll
    for (int r = 0; r < 8; r++) { bestv[r] = -INFINITY; besti[r] = 0; }

    for (int e0 = 0; e0 < NE; e0 += BN) {
        float acc[8][8];
#pragma unroll
        for (int r = 0; r < 8; r++)
#pragma unroll
            for (int c = 0; c < 8; c++) acc[r][c] = 0.0f;

        for (int kt = 0; kt < D; kt += KT) {
            // stage e tile: [BN][KT] -> e_s[c][EPAD]
            for (int i = tid; i < BN * KT / 4; i += 256) {
                int c = i / (KT / 4);
                int q = i % (KT / 4);
                float4 v = *(const float4*)(emb + (size_t)(e0 + c) * D + kt + q * 4);
                *(float4*)(e_s + c * EPAD + q * 4) = v;
            }
            __syncthreads();

            for (int kk = 0; kk < KT; kk += 4) {
                float4 zv[8], ev[8];
#pragma unroll
                for (int r = 0; r < 8; r++)
                    zv[r] = *(const float4*)(z_s + (ty * 8 + r) * D + kt + kk);
#pragma unroll
                for (int c = 0; c < 8; c++)
                    ev[c] = *(const float4*)(e_s + (tx + 32 * c) * EPAD + kk);
#pragma unroll
                for (int r = 0; r < 8; r++)
#pragma unroll
                    for (int c = 0; c < 8; c++) {
                        acc[r][c] = fmaf(zv[r].x, ev[c].x, acc[r][c]);
                        acc[r][c] = fmaf(zv[r].y, ev[c].y, acc[r][c]);
                        acc[r][c] = fmaf(zv[r].z, ev[c].z, acc[r][c]);
                        acc[r][c] = fmaf(zv[r].w, ev[c].w, acc[r][c]);
                    }
            }
            __syncthreads();
        }

        // scale by 1/||emb|| and update running argmax
#pragma unroll
        for (int c = 0; c < 8; c++) {
            int   col = e0 + tx + 32 * c;
            float inv = __ldg(&g_inv[col]);
#pragma unroll
            for (int r = 0; r < 8; r++) {
                float s = acc[r][c] * inv;
                if (s > bestv[r] || (s == bestv[r] && col < besti[r])) {
                    bestv[r] = s;
                    besti[r] = col;
                }
            }
        }
    }

    // cross-thread (tx) reduction per row — reuse e_s region
    float* sv = e_s;                        // [BM][32]
    int*   si = (int*)(e_s + BM * 32);      // [BM][32]
    __syncthreads();
#pragma unroll
    for (int r = 0; r < 8; r++) {
        sv[(ty * 8 + r) * 32 + tx] = bestv[r];
        si[(ty * 8 + r) * 32 + tx] = besti[r];
    }
    __syncthreads();
    if (tid < BM) {
        float bv = -INFINITY;
        int   bi = 0x7fffffff;
        for (int j = 0; j < 32; j++) {
            float v = sv[tid * 32 + j];
            int   ii = si[tid * 32 + j];
            if (v > bv || (v == bv && ii < bi)) { bv = v; bi = ii; }
        }
        g_idx[row0 + tid] = bi;
    }
}

// ---------------- gather + z_q_st + loss + counts + idx out ----------------
__global__ void gather_kernel(const float* __restrict__ z,
                              const float* __restrict__ emb,
                              float* __restrict__ out_zq,   // (may be unaligned base)
                              float* __restrict__ out_idx) {
    __shared__ float sred[4];
    __shared__ float sbc;
    int n = blockIdx.x;
    int t = threadIdx.x;   // 128 threads, 4 floats each
    int e = g_idx[n];
    float inv_e = g_inv[e];

    float4 zv = ((const float4*)(z + (size_t)n * D))[t];
    float ss = zv.x * zv.x + zv.y * zv.y + zv.z * zv.z + zv.w * zv.w;
    for (int o = 16; o; o >>= 1) ss += __shfl_down_sync(0xffffffffu, ss, o);
    if ((t & 31) == 0) sred[t >> 5] = ss;
    __syncthreads();
    if (t == 0) sbc = sred[0] + sred[1] + sred[2] + sred[3];
    __syncthreads();
    float zinv = 1.0f / fmaxf(sqrtf(sbc), 1e-12f);

    float4 q = ((const float4*)(emb + (size_t)e * D))[t];
    q.x *= inv_e; q.y *= inv_e; q.z *= inv_e; q.w *= inv_e;

    // scalar stores: out_zq base = d_out+1 is only 4B aligned
    float* o = out_zq + (size_t)n * D + t * 4;
    o[0] = q.x; o[1] = q.y; o[2] = q.z; o[3] = q.w;

    float dx = q.x - zv.x * zinv;
    float dy = q.y - zv.y * zinv;
    float dz = q.z - zv.z * zinv;
    float dw = q.w - zv.w * zinv;
    float ls = dx * dx + dy * dy + dz * dz + dw * dw;
    for (int o2 = 16; o2; o2 >>= 1) ls += __shfl_down_sync(0xffffffffu, ls, o2);
    if ((t & 31) == 0) sred[t >> 5] = ls;
    __syncthreads();
    if (t == 0) {
        atomicAdd(&g_loss, sred[0] + sred[1] + sred[2] + sred[3]);
        atomicAdd(&g_counts[e], 1.0f);
        out_idx[n] = (float)e;
    }
}

// ---------------- loss / perplexity finalize ----------------
__global__ void finalize_kernel(float* __restrict__ out, int N) {
    __shared__ float sh[256];
    float h = 0.0f;
    float invN = 1.0f / (float)N;
    for (int i = threadIdx.x; i < NE; i += 256) {
        float p = g_counts[i] * invN;
        h -= p * logf(p + 1e-10f);
    }
    sh[threadIdx.x] = h;
    __syncthreads();
    for (int s = 128; s; s >>= 1) {
        if (threadIdx.x < s) sh[threadIdx.x] += sh[threadIdx.x + s];
        __syncthreads();
    }
    if (threadIdx.x == 0) {
        out[0] = g_loss * (1.0f + BETA) / ((float)N * (float)D);
        out[1 + (size_t)N * D + (size_t)N] = expf(sh[0]);
    }
}

// ---------------- launch ----------------
extern "C" void kernel_launch(void* const* d_in, const int* in_sizes, int n_in,
                              void* d_out, int out_size) {
    const float* z   = (const float*)d_in[0];
    const float* emb = (const float*)d_in[1];
    float* out = (float*)d_out;

    int ND = in_sizes[0];
    int N  = ND / D;            // 32768

    size_t smem = (size_t)(BM * D + BN * EPAD) * sizeof(float);
    cudaFuncSetAttribute(argmax_kernel,
                         cudaFuncAttributeMaxDynamicSharedMemorySize, (int)smem);

    zero_kernel<<<(NE + 255) / 256, 256>>>();
    embnorm_kernel<<<NE, 128>>>(emb);
    argmax_kernel<<<N / BM, 256, smem>>>(z, emb);
    // output layout (tuple order, all as float32):
    // [0] loss | [1 .. 1+N*D) z_q_st | [1+N*D .. 1+N*D+N) idx | [last] perplexity
    gather_kernel<<<N, 128>>>(z, emb, out + 1, out + 1 + (size_t)ND);
    finalize_kernel<<<1, 256>>>(out, N);
}